// round 2
// baseline (speedup 1.0000x reference)
#include <cuda_runtime.h>
#include <cuda_bf16.h>
#include <math.h>

// ---------------------------------------------------------------------------
// Problem constants
// ---------------------------------------------------------------------------
#define BSZ   2
#define LEN   2048
#define DMODEL 1024
#define NHEAD 16
#define DK    64
#define FF    2730
#define FFP   2732                 // padded leading dim (multiple of 4 floats)
#define ROWS  (BSZ * LEN)          // 4096
#define EPS   1e-6f

// ---------------------------------------------------------------------------
// Scratch buffers (device globals: allocation-free)
// ---------------------------------------------------------------------------
__device__ float g_xn  [(size_t)ROWS * DMODEL];      // rmsnorm output (reused)
__device__ float g_qkv [(size_t)ROWS * 3 * DMODEL];  // qkv projection
__device__ float g_attn[(size_t)ROWS * DMODEL];      // attention output
__device__ float g_x1  [(size_t)ROWS * DMODEL];      // first residual
__device__ float g_h1  [(size_t)ROWS * FFP];         // w1 branch / gated (padded ld)
__device__ float g_h3  [(size_t)ROWS * FFP];         // w3 branch (padded ld)
__device__ float g_w2p [(size_t)DMODEL * FFP];       // w2 repacked with padded ld

// ---------------------------------------------------------------------------
// Repack w2 [D][FF] -> w2p [D][FFP] so float4 row loads are 16B-aligned.
// ---------------------------------------------------------------------------
__global__ void __launch_bounds__(256) repack_w2(const float* __restrict__ w2,
                                                 float* __restrict__ w2p)
{
    int row = blockIdx.x;
    const float* src = w2 + (size_t)row * FF;
    float* dst = w2p + (size_t)row * FFP;
    for (int k = threadIdx.x; k < FF; k += 256)
        dst[k] = src[k];
}

// ---------------------------------------------------------------------------
// RMSNorm: one block per row (D=1024, 256 threads x float4)
// ---------------------------------------------------------------------------
__global__ void __launch_bounds__(256) rmsnorm_k(const float* __restrict__ x,
                                                 const float* __restrict__ w,
                                                 float* __restrict__ y)
{
    int row = blockIdx.x;
    const float* xr = x + (size_t)row * DMODEL;
    float*       yr = y + (size_t)row * DMODEL;
    int t = threadIdx.x;

    float4 v = ((const float4*)xr)[t];
    float ss = v.x * v.x + v.y * v.y + v.z * v.z + v.w * v.w;
    #pragma unroll
    for (int o = 16; o; o >>= 1) ss += __shfl_xor_sync(0xffffffffu, ss, o);

    __shared__ float sred[8];
    if ((t & 31) == 0) sred[t >> 5] = ss;
    __syncthreads();
    float tot = 0.f;
    #pragma unroll
    for (int i = 0; i < 8; i++) tot += sred[i];

    float inv = rsqrtf(tot * (1.0f / DMODEL) + EPS);
    float4 wv = ((const float4*)w)[t];
    float4 r;
    r.x = v.x * inv * wv.x;
    r.y = v.y * inv * wv.y;
    r.z = v.z * inv * wv.z;
    r.w = v.w * inv * wv.w;
    ((float4*)yr)[t] = r;
}

// ---------------------------------------------------------------------------
// SGEMM NT:  C[M,N] = A[M,K] * B[N,K]^T  (+ optional residual R[M,N])
// BM=BN=128, BK=32, 256 threads, 8x8 micro-tile. M assumed multiple of 128.
// N and K fully guarded. lda/ldb/ldc must be multiples of 4 (float4 align).
// ---------------------------------------------------------------------------
template <int EPI>
__global__ void __launch_bounds__(256) sgemm_nt(const float* __restrict__ A, int lda,
                                                const float* __restrict__ B, int ldb,
                                                const float* __restrict__ R,
                                                float* __restrict__ C, int ldc,
                                                int M, int N, int K)
{
    const int BM = 128, BN = 128, BK = 32;
    __shared__ float As[BK][BM + 4];
    __shared__ float Bs[BK][BN + 4];

    int tid = threadIdx.x;
    int tx = tid & 15;          // n micro
    int ty = tid >> 4;          // m micro
    int lrow = tid >> 3;        // 0..31
    int lcol = (tid & 7) * 4;   // 0,4,...,28

    const int m0 = blockIdx.y * BM;
    const int n0 = blockIdx.x * BN;

    float acc[8][8];
    #pragma unroll
    for (int i = 0; i < 8; i++)
        #pragma unroll
        for (int j = 0; j < 8; j++) acc[i][j] = 0.f;

    for (int k0 = 0; k0 < K; k0 += BK) {
        // --- stage A tile (transposed) ---
        #pragma unroll
        for (int i = 0; i < 4; i++) {
            int m = m0 + lrow + i * 32;
            int k = k0 + lcol;
            float4 v = make_float4(0.f, 0.f, 0.f, 0.f);
            const float* ap = A + (size_t)m * lda + k;
            if (k + 3 < K) {
                v = *(const float4*)ap;
            } else {
                if (k + 0 < K) v.x = ap[0];
                if (k + 1 < K) v.y = ap[1];
                if (k + 2 < K) v.z = ap[2];
                if (k + 3 < K) v.w = ap[3];
            }
            As[lcol + 0][lrow + i * 32] = v.x;
            As[lcol + 1][lrow + i * 32] = v.y;
            As[lcol + 2][lrow + i * 32] = v.z;
            As[lcol + 3][lrow + i * 32] = v.w;
        }
        // --- stage B tile (transposed) ---
        #pragma unroll
        for (int i = 0; i < 4; i++) {
            int n = n0 + lrow + i * 32;
            int k = k0 + lcol;
            float4 v = make_float4(0.f, 0.f, 0.f, 0.f);
            if (n < N) {
                const float* bp = B + (size_t)n * ldb + k;
                if (k + 3 < K) {
                    v = *(const float4*)bp;
                } else {
                    if (k + 0 < K) v.x = bp[0];
                    if (k + 1 < K) v.y = bp[1];
                    if (k + 2 < K) v.z = bp[2];
                    if (k + 3 < K) v.w = bp[3];
                }
            }
            Bs[lcol + 0][lrow + i * 32] = v.x;
            Bs[lcol + 1][lrow + i * 32] = v.y;
            Bs[lcol + 2][lrow + i * 32] = v.z;
            Bs[lcol + 3][lrow + i * 32] = v.w;
        }
        __syncthreads();

        #pragma unroll
        for (int kk = 0; kk < BK; kk++) {
            float a[8], bb[8];
            *(float4*)(a)     = *(const float4*)&As[kk][ty * 8];
            *(float4*)(a + 4) = *(const float4*)&As[kk][ty * 8 + 4];
            *(float4*)(bb)     = *(const float4*)&Bs[kk][tx * 8];
            *(float4*)(bb + 4) = *(const float4*)&Bs[kk][tx * 8 + 4];
            #pragma unroll
            for (int i = 0; i < 8; i++)
                #pragma unroll
                for (int j = 0; j < 8; j++)
                    acc[i][j] += a[i] * bb[j];
        }
        __syncthreads();
    }

    // --- epilogue ---
    #pragma unroll
    for (int i = 0; i < 8; i++) {
        int m = m0 + ty * 8 + i;
        if (m >= M) continue;
        #pragma unroll
        for (int j = 0; j < 8; j++) {
            int n = n0 + tx * 8 + j;
            if (n < N) {
                float v = acc[i][j];
                if (EPI == 1) v += R[(size_t)m * ldc + n];
                C[(size_t)m * ldc + n] = v;
            }
        }
    }
}

// ---------------------------------------------------------------------------
// Flash attention (fp32, online softmax).
// grid = (L/64 query tiles, B*H), block = 128 threads.
// Dynamic smem layout (floats):
//   Qt [64][64]  at 0       (Q^T, pre-scaled by 1/sqrt(DK))
//   Kt [64][68]  at 4096    (K^T, padded; reused as P^T after S compute)
//   Vs [64][64]  at 8448    (V row-major)
// total 12544 floats = 50176 bytes.
// ---------------------------------------------------------------------------
#define FLASH_SMEM (12544 * 4)
#define QT(k, m) sm[(k) * 64 + (m)]
#define KT(k, n) sm[4096 + (k) * 68 + (n)]
#define PT(j, m) sm[4096 + (j) * 68 + (m)]
#define VS(j, d) sm[8448 + (j) * 64 + (d)]

__global__ void __launch_bounds__(128) flash_attn(const float* __restrict__ qkv,
                                                  float* __restrict__ out)
{
    extern __shared__ float sm[];

    int bh = blockIdx.y;
    int b = bh >> 4;
    int h = bh & 15;
    int q0 = blockIdx.x * 64;

    const float* qbase = qkv + (size_t)b * LEN * (3 * DMODEL) + h * DK;
    const float* kbase = qbase + DMODEL;
    const float* vbase = qbase + 2 * DMODEL;

    int tid = threadIdx.x;
    int tx = tid & 15;   // key/d micro column (x4)
    int ty = tid >> 4;   // query micro row (x8)

    // load Q tile (transposed, scaled)
    {
        int r = tid >> 4;         // 0..7
        int c = (tid & 15) * 4;   // 0..60
        #pragma unroll
        for (int i = 0; i < 8; i++) {
            int row = r + i * 8;
            float4 v = *(const float4*)(qbase + (size_t)(q0 + row) * (3 * DMODEL) + c);
            QT(c + 0, row) = v.x * 0.125f;
            QT(c + 1, row) = v.y * 0.125f;
            QT(c + 2, row) = v.z * 0.125f;
            QT(c + 3, row) = v.w * 0.125f;
        }
    }

    float m_i[8], l_i[8], o[8][4];
    #pragma unroll
    for (int i = 0; i < 8; i++) {
        m_i[i] = -1e30f;
        l_i[i] = 0.f;
        o[i][0] = o[i][1] = o[i][2] = o[i][3] = 0.f;
    }

    for (int kt = 0; kt < LEN; kt += 64) {
        __syncthreads();   // prior P@V reads of Kt/Vs done
        // load K (transposed) and V (row-major) tiles
        {
            int r = tid >> 4;
            int c = (tid & 15) * 4;
            #pragma unroll
            for (int i = 0; i < 8; i++) {
                int row = r + i * 8;
                float4 kv = *(const float4*)(kbase + (size_t)(kt + row) * (3 * DMODEL) + c);
                KT(c + 0, row) = kv.x;
                KT(c + 1, row) = kv.y;
                KT(c + 2, row) = kv.z;
                KT(c + 3, row) = kv.w;
                float4 vv = *(const float4*)(vbase + (size_t)(kt + row) * (3 * DMODEL) + c);
                *(float4*)&VS(row, c) = vv;
            }
        }
        __syncthreads();

        // S = Q K^T  (64x64x64), per-thread 8x4
        float s[8][4];
        #pragma unroll
        for (int i = 0; i < 8; i++)
            s[i][0] = s[i][1] = s[i][2] = s[i][3] = 0.f;
        #pragma unroll
        for (int kk = 0; kk < 64; kk++) {
            float a[8], bb[4];
            *(float4*)(a)     = *(const float4*)&QT(kk, ty * 8);
            *(float4*)(a + 4) = *(const float4*)&QT(kk, ty * 8 + 4);
            *(float4*)(bb)    = *(const float4*)&KT(kk, tx * 4);
            #pragma unroll
            for (int i = 0; i < 8; i++)
                #pragma unroll
                for (int j = 0; j < 4; j++)
                    s[i][j] += a[i] * bb[j];
        }

        // online softmax (rows span 16 lanes: shuffle-reduce)
        #pragma unroll
        for (int i = 0; i < 8; i++) {
            float mx = fmaxf(fmaxf(s[i][0], s[i][1]), fmaxf(s[i][2], s[i][3]));
            #pragma unroll
            for (int off = 8; off >= 1; off >>= 1)
                mx = fmaxf(mx, __shfl_xor_sync(0xffffffffu, mx, off));
            float mnew = fmaxf(m_i[i], mx);
            float corr = __expf(m_i[i] - mnew);
            m_i[i] = mnew;
            float rs = 0.f;
            #pragma unroll
            for (int j = 0; j < 4; j++) {
                s[i][j] = __expf(s[i][j] - mnew);
                rs += s[i][j];
            }
            #pragma unroll
            for (int off = 8; off >= 1; off >>= 1)
                rs += __shfl_xor_sync(0xffffffffu, rs, off);
            l_i[i] = l_i[i] * corr + rs;
            o[i][0] *= corr; o[i][1] *= corr; o[i][2] *= corr; o[i][3] *= corr;
        }

        __syncthreads();   // all Kt reads done before P^T overwrites it
        #pragma unroll
        for (int i = 0; i < 8; i++)
            #pragma unroll
            for (int j = 0; j < 4; j++)
                PT(tx * 4 + j, ty * 8 + i) = s[i][j];
        __syncthreads();

        // O += P V  (64x64x64), per-thread 8x4
        #pragma unroll 8
        for (int j = 0; j < 64; j++) {
            float a[8], bb[4];
            *(float4*)(a)     = *(const float4*)&PT(j, ty * 8);
            *(float4*)(a + 4) = *(const float4*)&PT(j, ty * 8 + 4);
            *(float4*)(bb)    = *(const float4*)&VS(j, tx * 4);
            #pragma unroll
            for (int i = 0; i < 8; i++)
                #pragma unroll
                for (int jj = 0; jj < 4; jj++)
                    o[i][jj] += a[i] * bb[jj];
        }
    }

    // finalize & store
    #pragma unroll
    for (int i = 0; i < 8; i++) {
        float invl = 1.0f / l_i[i];
        float4 r;
        r.x = o[i][0] * invl;
        r.y = o[i][1] * invl;
        r.z = o[i][2] * invl;
        r.w = o[i][3] * invl;
        int row = q0 + ty * 8 + i;
        *(float4*)(out + (size_t)(b * LEN + row) * DMODEL + h * DK + tx * 4) = r;
    }
}

// ---------------------------------------------------------------------------
// SwiGLU gate: h1 = silu(h1) * h3  (over padded rows; pads never read)
// ---------------------------------------------------------------------------
__global__ void __launch_bounds__(256) silu_mul(float* __restrict__ h1,
                                                const float* __restrict__ h3)
{
    int row = blockIdx.x;
    float* a = h1 + (size_t)row * FFP;
    const float* b = h3 + (size_t)row * FFP;
    for (int k = threadIdx.x; k < FF; k += 256) {
        float v = a[k];
        float g = v / (1.0f + __expf(-v));
        a[k] = g * b[k];
    }
}

// ---------------------------------------------------------------------------
// Launch
// ---------------------------------------------------------------------------
extern "C" void kernel_launch(void* const* d_in, const int* in_sizes, int n_in,
                              void* d_out, int out_size)
{
    const float* x     = (const float*)d_in[0];
    const float* w_qkv = (const float*)d_in[1];
    const float* w_o   = (const float*)d_in[2];
    const float* n1_w  = (const float*)d_in[3];
    const float* n2_w  = (const float*)d_in[4];
    const float* w1    = (const float*)d_in[5];
    const float* w2    = (const float*)d_in[6];
    const float* w3    = (const float*)d_in[7];
    float* out = (float*)d_out;

    cudaFuncSetAttribute(flash_attn, cudaFuncAttributeMaxDynamicSharedMemorySize,
                         FLASH_SMEM);

    float *xn, *qkv, *attn, *x1, *h1, *h3, *w2p;
    cudaGetSymbolAddress((void**)&xn,   g_xn);
    cudaGetSymbolAddress((void**)&qkv,  g_qkv);
    cudaGetSymbolAddress((void**)&attn, g_attn);
    cudaGetSymbolAddress((void**)&x1,   g_x1);
    cudaGetSymbolAddress((void**)&h1,   g_h1);
    cudaGetSymbolAddress((void**)&h3,   g_h3);
    cudaGetSymbolAddress((void**)&w2p,  g_w2p);

    // repack w2 to padded leading dim (alignment for float4 loads)
    repack_w2<<<DMODEL, 256>>>(w2, w2p);

    // x̂1 = rmsnorm(x, n1)
    rmsnorm_k<<<ROWS, 256>>>(x, n1_w, xn);
    // qkv = x̂1 @ w_qkv^T
    sgemm_nt<0><<<dim3(3 * DMODEL / 128, ROWS / 128), 256>>>(
        xn, DMODEL, w_qkv, DMODEL, nullptr, qkv, 3 * DMODEL,
        ROWS, 3 * DMODEL, DMODEL);
    // attention
    flash_attn<<<dim3(LEN / 64, BSZ * NHEAD), 128, FLASH_SMEM>>>(qkv, attn);
    // x1 = x + attn @ w_o^T
    sgemm_nt<1><<<dim3(DMODEL / 128, ROWS / 128), 256>>>(
        attn, DMODEL, w_o, DMODEL, x, x1, DMODEL,
        ROWS, DMODEL, DMODEL);
    // x̂2 = rmsnorm(x1, n2)
    rmsnorm_k<<<ROWS, 256>>>(x1, n2_w, xn);
    // h1 = x̂2 @ w1^T ; h3 = x̂2 @ w3^T   (outputs with padded ld = FFP)
    sgemm_nt<0><<<dim3((FF + 127) / 128, ROWS / 128), 256>>>(
        xn, DMODEL, w1, DMODEL, nullptr, h1, FFP,
        ROWS, FF, DMODEL);
    sgemm_nt<0><<<dim3((FF + 127) / 128, ROWS / 128), 256>>>(
        xn, DMODEL, w3, DMODEL, nullptr, h3, FFP,
        ROWS, FF, DMODEL);
    // h1 = silu(h1) * h3
    silu_mul<<<ROWS, 256>>>(h1, h3);
    // out = x1 + h1 @ w2p^T
    sgemm_nt<1><<<dim3(DMODEL / 128, ROWS / 128), 256>>>(
        h1, FFP, w2p, FFP, x1, out, DMODEL,
        ROWS, DMODEL, FF);
}

// round 4
// speedup vs baseline: 1.8144x; 1.8144x over previous
#include <cuda_runtime.h>
#include <cuda_bf16.h>
#include <math.h>
#include <stdint.h>

// ---------------------------------------------------------------------------
// Problem constants
// ---------------------------------------------------------------------------
#define BSZ    2
#define LEN    2048
#define DMODEL 1024
#define NHEAD  16
#define DK     64
#define FF     2730
#define FF_PAD 2816                // 22*128
#define ROWS   (BSZ * LEN)         // 4096
#define EPS    1e-6f

// ---------------------------------------------------------------------------
// Scratch (device globals: allocation-free)
// ---------------------------------------------------------------------------
__device__ float g_qkv [(size_t)ROWS * 3 * DMODEL];
__device__ float g_attn[(size_t)ROWS * DMODEL];
__device__ float g_x1  [(size_t)ROWS * DMODEL];
__device__ float g_h1  [(size_t)ROWS * FF_PAD];
__device__ float g_h3  [(size_t)ROWS * FF_PAD];

__device__ __nv_bfloat16 g_xn_h[(size_t)ROWS * DMODEL];
__device__ __nv_bfloat16 g_xn_l[(size_t)ROWS * DMODEL];
__device__ __nv_bfloat16 g_at_h[(size_t)ROWS * DMODEL];
__device__ __nv_bfloat16 g_at_l[(size_t)ROWS * DMODEL];
__device__ __nv_bfloat16 g_gt_h[(size_t)ROWS * FF_PAD];
__device__ __nv_bfloat16 g_gt_l[(size_t)ROWS * FF_PAD];

__device__ __nv_bfloat16 g_wq_h[(size_t)3 * DMODEL * DMODEL];
__device__ __nv_bfloat16 g_wq_l[(size_t)3 * DMODEL * DMODEL];
__device__ __nv_bfloat16 g_wo_h[(size_t)DMODEL * DMODEL];
__device__ __nv_bfloat16 g_wo_l[(size_t)DMODEL * DMODEL];
__device__ __nv_bfloat16 g_w1_h[(size_t)FF_PAD * DMODEL];
__device__ __nv_bfloat16 g_w1_l[(size_t)FF_PAD * DMODEL];
__device__ __nv_bfloat16 g_w3_h[(size_t)FF_PAD * DMODEL];
__device__ __nv_bfloat16 g_w3_l[(size_t)FF_PAD * DMODEL];
__device__ __nv_bfloat16 g_w2_h[(size_t)DMODEL * FF_PAD];
__device__ __nv_bfloat16 g_w2_l[(size_t)DMODEL * FF_PAD];

// ---------------------------------------------------------------------------
// PTX helpers (sm_80+ portable: cp.async, ldmatrix, mma.sync)
// ---------------------------------------------------------------------------
__device__ __forceinline__ uint32_t smem_u32(const void* p) {
    uint32_t a;
    asm("{ .reg .u64 t; cvta.to.shared.u64 t, %1; cvt.u32.u64 %0, t; }"
        : "=r"(a) : "l"(p));
    return a;
}
__device__ __forceinline__ void cp16(uint32_t dst, const void* src) {
    asm volatile("cp.async.cg.shared.global [%0], [%1], 16;" :: "r"(dst), "l"(src));
}
__device__ __forceinline__ void ldmx4(uint32_t r[4], uint32_t addr) {
    asm volatile("ldmatrix.sync.aligned.m8n8.x4.shared.b16 {%0,%1,%2,%3}, [%4];"
                 : "=r"(r[0]), "=r"(r[1]), "=r"(r[2]), "=r"(r[3]) : "r"(addr));
}
__device__ __forceinline__ void mma_bf16(float c[4], const uint32_t a[4],
                                         uint32_t b0, uint32_t b1) {
    asm volatile(
        "mma.sync.aligned.m16n8k16.row.col.f32.bf16.bf16.f32 "
        "{%0,%1,%2,%3}, {%4,%5,%6,%7}, {%8,%9}, {%0,%1,%2,%3};"
        : "+f"(c[0]), "+f"(c[1]), "+f"(c[2]), "+f"(c[3])
        : "r"(a[0]), "r"(a[1]), "r"(a[2]), "r"(a[3]), "r"(b0), "r"(b1));
}

// ---------------------------------------------------------------------------
// bf16 hi/lo 3-pass MMA GEMM:  C[M,N] = (Ah+Al)[M,K] (Bh+Bl)[N,K]^T (+R)
// BM=BN=128, BK=32, 256 threads (8 warps, 2x4), warp tile 64x32.
// M,N multiples of 128; K multiple of 32; lda/ldb multiples of 8.
// ---------------------------------------------------------------------------
#define LDS_H   40                          // halves per smem row (padded)
#define TILE_SB (128 * LDS_H * 2)           // 10240 B per tile
#define STG_SB  (4 * TILE_SB)               // 40960 B per stage
#define GEMM_SMEM (2 * STG_SB)              // 81920 B

__global__ void __launch_bounds__(256, 1)
gemm_mma(const __nv_bfloat16* __restrict__ Ah, const __nv_bfloat16* __restrict__ Al,
         int lda,
         const __nv_bfloat16* __restrict__ Bh, const __nv_bfloat16* __restrict__ Bl,
         int ldb,
         const float* __restrict__ R, float* __restrict__ C, int ldc, int K)
{
    extern __shared__ char smraw[];
    uint32_t s0 = smem_u32(smraw);

    int tid = threadIdx.x;
    int wid = tid >> 5;
    int lane = tid & 31;
    int wm = wid >> 2;               // 0..1
    int wn = wid & 3;                // 0..3

    size_t m0 = (size_t)blockIdx.y * 128;
    size_t n0 = (size_t)blockIdx.x * 128;

    float acc[4][4][4];
    #pragma unroll
    for (int i = 0; i < 4; i++)
        #pragma unroll
        for (int j = 0; j < 4; j++)
            #pragma unroll
            for (int q = 0; q < 4; q++) acc[i][j][q] = 0.f;

    const int T = K >> 5;

    // stage loader: 512 chunks of 16B per tile, 2 iters x 4 tiles per thread
    auto load_stage = [&](int buf, int k0) {
        uint32_t sbase = s0 + buf * STG_SB;
        #pragma unroll
        for (int i = 0; i < 2; i++) {
            int c = tid + i * 256;       // 0..511
            int row = c >> 2;
            int c16 = c & 3;
            uint32_t off = (uint32_t)(row * (LDS_H * 2) + c16 * 16);
            size_t ga = (size_t)(m0 + row) * lda + k0 + c16 * 8;
            size_t gb = (size_t)(n0 + row) * ldb + k0 + c16 * 8;
            cp16(sbase + off,               Ah + ga);
            cp16(sbase + TILE_SB + off,     Al + ga);
            cp16(sbase + 2 * TILE_SB + off, Bh + gb);
            cp16(sbase + 3 * TILE_SB + off, Bl + gb);
        }
        asm volatile("cp.async.commit_group;");
    };

    load_stage(0, 0);

    int lr = lane & 15;
    int lc = (lane >> 4) * 8;        // 0 or 8 (halves)

    for (int t = 0; t < T; t++) {
        if (t + 1 < T) {
            load_stage((t + 1) & 1, (t + 1) << 5);
            asm volatile("cp.async.wait_group 1;");
        } else {
            asm volatile("cp.async.wait_group 0;");
        }
        __syncthreads();

        uint32_t base = s0 + (t & 1) * STG_SB;
        #pragma unroll
        for (int kk = 0; kk < 2; kk++) {
            int k16 = kk * 16;
            uint32_t ah[4][4], al[4][4], bh[2][4], bl[2][4];
            #pragma unroll
            for (int mi = 0; mi < 4; mi++) {
                uint32_t aoff = (uint32_t)((wm * 64 + mi * 16 + lr) * (LDS_H * 2) +
                                           (k16 + lc) * 2);
                ldmx4(ah[mi], base + aoff);
                ldmx4(al[mi], base + TILE_SB + aoff);
            }
            #pragma unroll
            for (int ni = 0; ni < 2; ni++) {
                uint32_t boff = (uint32_t)((wn * 32 + ni * 16 + lr) * (LDS_H * 2) +
                                           (k16 + lc) * 2);
                ldmx4(bh[ni], base + 2 * TILE_SB + boff);
                ldmx4(bl[ni], base + 3 * TILE_SB + boff);
            }
            #pragma unroll
            for (int mi = 0; mi < 4; mi++) {
                #pragma unroll
                for (int nj = 0; nj < 4; nj++) {
                    int ni = nj >> 1;
                    int sel = nj & 1;
                    mma_bf16(acc[mi][nj], ah[mi], bh[ni][sel], bh[ni][sel + 2]);
                    mma_bf16(acc[mi][nj], ah[mi], bl[ni][sel], bl[ni][sel + 2]);
                    mma_bf16(acc[mi][nj], al[mi], bh[ni][sel], bh[ni][sel + 2]);
                }
            }
        }
        __syncthreads();
    }

    // epilogue: c-frag -> gmem (float2 per frag half), optional residual
    int qr = lane >> 2;
    int qc = (lane & 3) * 2;
    #pragma unroll
    for (int mi = 0; mi < 4; mi++) {
        #pragma unroll
        for (int nj = 0; nj < 4; nj++) {
            size_t m = m0 + wm * 64 + mi * 16 + qr;
            size_t n = n0 + wn * 32 + nj * 8 + qc;
            float2 v0 = make_float2(acc[mi][nj][0], acc[mi][nj][1]);
            float2 v1 = make_float2(acc[mi][nj][2], acc[mi][nj][3]);
            if (R) {
                float2 r0 = *(const float2*)(R + m * ldc + n);
                float2 r1 = *(const float2*)(R + (m + 8) * ldc + n);
                v0.x += r0.x; v0.y += r0.y;
                v1.x += r1.x; v1.y += r1.y;
            }
            *(float2*)(C + m * ldc + n) = v0;
            *(float2*)(C + (m + 8) * ldc + n) = v1;
        }
    }
}

// ---------------------------------------------------------------------------
// fp32 -> bf16 hi/lo split with zero padding (generic). grid.x = rows_dst.
// ---------------------------------------------------------------------------
__global__ void __launch_bounds__(256) convert_split(const float* __restrict__ src,
                                                     int ld_src, int rows_src,
                                                     int cols_src,
                                                     __nv_bfloat16* __restrict__ hi,
                                                     __nv_bfloat16* __restrict__ lo,
                                                     int ld_dst)
{
    int r = blockIdx.x;
    const float* s = src + (size_t)r * ld_src;
    __nv_bfloat16* ph = hi + (size_t)r * ld_dst;
    __nv_bfloat16* pl = lo + (size_t)r * ld_dst;
    bool rv = r < rows_src;
    for (int c = threadIdx.x; c < ld_dst; c += 256) {
        float v = (rv && c < cols_src) ? s[c] : 0.f;
        __nv_bfloat16 h = __float2bfloat16(v);
        ph[c] = h;
        pl[c] = __float2bfloat16(v - __bfloat162float(h));
    }
}

// ---------------------------------------------------------------------------
// RMSNorm with fused hi/lo split output
// ---------------------------------------------------------------------------
__global__ void __launch_bounds__(256) rmsnorm_split(const float* __restrict__ x,
                                                     const float* __restrict__ w,
                                                     __nv_bfloat16* __restrict__ hi,
                                                     __nv_bfloat16* __restrict__ lo)
{
    int row = blockIdx.x;
    const float* xr = x + (size_t)row * DMODEL;
    int t = threadIdx.x;

    float4 v = ((const float4*)xr)[t];
    float ss = v.x * v.x + v.y * v.y + v.z * v.z + v.w * v.w;
    #pragma unroll
    for (int o = 16; o; o >>= 1) ss += __shfl_xor_sync(0xffffffffu, ss, o);
    __shared__ float sred[8];
    if ((t & 31) == 0) sred[t >> 5] = ss;
    __syncthreads();
    float tot = 0.f;
    #pragma unroll
    for (int i = 0; i < 8; i++) tot += sred[i];
    float inv = rsqrtf(tot * (1.0f / DMODEL) + EPS);

    float4 wv = ((const float4*)w)[t];
    float o4[4] = { v.x * inv * wv.x, v.y * inv * wv.y,
                    v.z * inv * wv.z, v.w * inv * wv.w };
    size_t base = (size_t)row * DMODEL + t * 4;
    #pragma unroll
    for (int j = 0; j < 4; j++) {
        __nv_bfloat16 h = __float2bfloat16(o4[j]);
        hi[base + j] = h;
        lo[base + j] = __float2bfloat16(o4[j] - __bfloat162float(h));
    }
}

// ---------------------------------------------------------------------------
// SwiGLU gate with fused hi/lo split: g = silu(h1)*h3
// ---------------------------------------------------------------------------
__global__ void __launch_bounds__(256) silu_gate_split(const float* __restrict__ h1,
                                                       const float* __restrict__ h3,
                                                       __nv_bfloat16* __restrict__ hi,
                                                       __nv_bfloat16* __restrict__ lo)
{
    int row = blockIdx.x;
    const float* a = h1 + (size_t)row * FF_PAD;
    const float* b = h3 + (size_t)row * FF_PAD;
    __nv_bfloat16* ph = hi + (size_t)row * FF_PAD;
    __nv_bfloat16* pl = lo + (size_t)row * FF_PAD;
    for (int c = threadIdx.x; c < FF_PAD; c += 256) {
        float v = a[c];
        float g = v / (1.0f + __expf(-v)) * b[c];
        __nv_bfloat16 h = __float2bfloat16(g);
        ph[c] = h;
        pl[c] = __float2bfloat16(g - __bfloat162float(h));
    }
}

// ---------------------------------------------------------------------------
// Flash attention (fp32, online softmax) — unchanged
// ---------------------------------------------------------------------------
#define FLASH_SMEM (12544 * 4)
#define QT(k, m) sm[(k) * 64 + (m)]
#define KT(k, n) sm[4096 + (k) * 68 + (n)]
#define PT(j, m) sm[4096 + (j) * 68 + (m)]
#define VS(j, d) sm[8448 + (j) * 64 + (d)]

__global__ void __launch_bounds__(128) flash_attn(const float* __restrict__ qkv,
                                                  float* __restrict__ out)
{
    extern __shared__ float sm[];

    int bh = blockIdx.y;
    int b = bh >> 4;
    int h = bh & 15;
    int q0 = blockIdx.x * 64;

    const float* qbase = qkv + (size_t)b * LEN * (3 * DMODEL) + h * DK;
    const float* kbase = qbase + DMODEL;
    const float* vbase = qbase + 2 * DMODEL;

    int tid = threadIdx.x;
    int tx = tid & 15;
    int ty = tid >> 4;

    {
        int r = tid >> 4;
        int c = (tid & 15) * 4;
        #pragma unroll
        for (int i = 0; i < 8; i++) {
            int row = r + i * 8;
            float4 v = *(const float4*)(qbase + (size_t)(q0 + row) * (3 * DMODEL) + c);
            QT(c + 0, row) = v.x * 0.125f;
            QT(c + 1, row) = v.y * 0.125f;
            QT(c + 2, row) = v.z * 0.125f;
            QT(c + 3, row) = v.w * 0.125f;
        }
    }

    float m_i[8], l_i[8], o[8][4];
    #pragma unroll
    for (int i = 0; i < 8; i++) {
        m_i[i] = -1e30f;
        l_i[i] = 0.f;
        o[i][0] = o[i][1] = o[i][2] = o[i][3] = 0.f;
    }

    for (int kt = 0; kt < LEN; kt += 64) {
        __syncthreads();
        {
            int r = tid >> 4;
            int c = (tid & 15) * 4;
            #pragma unroll
            for (int i = 0; i < 8; i++) {
                int row = r + i * 8;
                float4 kv = *(const float4*)(kbase + (size_t)(kt + row) * (3 * DMODEL) + c);
                KT(c + 0, row) = kv.x;
                KT(c + 1, row) = kv.y;
                KT(c + 2, row) = kv.z;
                KT(c + 3, row) = kv.w;
                float4 vv = *(const float4*)(vbase + (size_t)(kt + row) * (3 * DMODEL) + c);
                *(float4*)&VS(row, c) = vv;
            }
        }
        __syncthreads();

        float s[8][4];
        #pragma unroll
        for (int i = 0; i < 8; i++)
            s[i][0] = s[i][1] = s[i][2] = s[i][3] = 0.f;
        #pragma unroll
        for (int kk = 0; kk < 64; kk++) {
            float a[8], bb[4];
            *(float4*)(a)     = *(const float4*)&QT(kk, ty * 8);
            *(float4*)(a + 4) = *(const float4*)&QT(kk, ty * 8 + 4);
            *(float4*)(bb)    = *(const float4*)&KT(kk, tx * 4);
            #pragma unroll
            for (int i = 0; i < 8; i++)
                #pragma unroll
                for (int j = 0; j < 4; j++)
                    s[i][j] += a[i] * bb[j];
        }

        #pragma unroll
        for (int i = 0; i < 8; i++) {
            float mx = fmaxf(fmaxf(s[i][0], s[i][1]), fmaxf(s[i][2], s[i][3]));
            #pragma unroll
            for (int off = 8; off >= 1; off >>= 1)
                mx = fmaxf(mx, __shfl_xor_sync(0xffffffffu, mx, off));
            float mnew = fmaxf(m_i[i], mx);
            float corr = __expf(m_i[i] - mnew);
            m_i[i] = mnew;
            float rs = 0.f;
            #pragma unroll
            for (int j = 0; j < 4; j++) {
                s[i][j] = __expf(s[i][j] - mnew);
                rs += s[i][j];
            }
            #pragma unroll
            for (int off = 8; off >= 1; off >>= 1)
                rs += __shfl_xor_sync(0xffffffffu, rs, off);
            l_i[i] = l_i[i] * corr + rs;
            o[i][0] *= corr; o[i][1] *= corr; o[i][2] *= corr; o[i][3] *= corr;
        }

        __syncthreads();
        #pragma unroll
        for (int i = 0; i < 8; i++)
            #pragma unroll
            for (int j = 0; j < 4; j++)
                PT(tx * 4 + j, ty * 8 + i) = s[i][j];
        __syncthreads();

        #pragma unroll 8
        for (int j = 0; j < 64; j++) {
            float a[8], bb[4];
            *(float4*)(a)     = *(const float4*)&PT(j, ty * 8);
            *(float4*)(a + 4) = *(const float4*)&PT(j, ty * 8 + 4);
            *(float4*)(bb)    = *(const float4*)&VS(j, tx * 4);
            #pragma unroll
            for (int i = 0; i < 8; i++)
                #pragma unroll
                for (int jj = 0; jj < 4; jj++)
                    o[i][jj] += a[i] * bb[jj];
        }
    }

    #pragma unroll
    for (int i = 0; i < 8; i++) {
        float invl = 1.0f / l_i[i];
        float4 r;
        r.x = o[i][0] * invl;
        r.y = o[i][1] * invl;
        r.z = o[i][2] * invl;
        r.w = o[i][3] * invl;
        int row = q0 + ty * 8 + i;
        *(float4*)(out + (size_t)(b * LEN + row) * DMODEL + h * DK + tx * 4) = r;
    }
}

// ---------------------------------------------------------------------------
// Launch
// ---------------------------------------------------------------------------
extern "C" void kernel_launch(void* const* d_in, const int* in_sizes, int n_in,
                              void* d_out, int out_size)
{
    const float* x     = (const float*)d_in[0];
    const float* w_qkv = (const float*)d_in[1];
    const float* w_o   = (const float*)d_in[2];
    const float* n1_w  = (const float*)d_in[3];
    const float* n2_w  = (const float*)d_in[4];
    const float* w1    = (const float*)d_in[5];
    const float* w2    = (const float*)d_in[6];
    const float* w3    = (const float*)d_in[7];
    float* out = (float*)d_out;

    cudaFuncSetAttribute(flash_attn, cudaFuncAttributeMaxDynamicSharedMemorySize,
                         FLASH_SMEM);
    cudaFuncSetAttribute(gemm_mma, cudaFuncAttributeMaxDynamicSharedMemorySize,
                         GEMM_SMEM);

    float *qkv, *attn, *x1, *h1, *h3;
    cudaGetSymbolAddress((void**)&qkv,  g_qkv);
    cudaGetSymbolAddress((void**)&attn, g_attn);
    cudaGetSymbolAddress((void**)&x1,   g_x1);
    cudaGetSymbolAddress((void**)&h1,   g_h1);
    cudaGetSymbolAddress((void**)&h3,   g_h3);

    __nv_bfloat16 *xnh, *xnl, *ath, *atl, *gth, *gtl;
    __nv_bfloat16 *wqh, *wql, *woh, *wol, *w1h, *w1l, *w3h, *w3l, *w2h, *w2l;
    cudaGetSymbolAddress((void**)&xnh, g_xn_h); cudaGetSymbolAddress((void**)&xnl, g_xn_l);
    cudaGetSymbolAddress((void**)&ath, g_at_h); cudaGetSymbolAddress((void**)&atl, g_at_l);
    cudaGetSymbolAddress((void**)&gth, g_gt_h); cudaGetSymbolAddress((void**)&gtl, g_gt_l);
    cudaGetSymbolAddress((void**)&wqh, g_wq_h); cudaGetSymbolAddress((void**)&wql, g_wq_l);
    cudaGetSymbolAddress((void**)&woh, g_wo_h); cudaGetSymbolAddress((void**)&wol, g_wo_l);
    cudaGetSymbolAddress((void**)&w1h, g_w1_h); cudaGetSymbolAddress((void**)&w1l, g_w1_l);
    cudaGetSymbolAddress((void**)&w3h, g_w3_h); cudaGetSymbolAddress((void**)&w3l, g_w3_l);
    cudaGetSymbolAddress((void**)&w2h, g_w2_h); cudaGetSymbolAddress((void**)&w2l, g_w2_l);

    // weight conversions (hi/lo bf16, zero-padded)
    convert_split<<<3 * DMODEL, 256>>>(w_qkv, DMODEL, 3 * DMODEL, DMODEL, wqh, wql, DMODEL);
    convert_split<<<DMODEL, 256>>>(w_o, DMODEL, DMODEL, DMODEL, woh, wol, DMODEL);
    convert_split<<<FF_PAD, 256>>>(w1, DMODEL, FF, DMODEL, w1h, w1l, DMODEL);
    convert_split<<<FF_PAD, 256>>>(w3, DMODEL, FF, DMODEL, w3h, w3l, DMODEL);
    convert_split<<<DMODEL, 256>>>(w2, FF, DMODEL, FF, w2h, w2l, FF_PAD);

    // x̂1 = rmsnorm(x, n1)  (bf16 hi/lo)
    rmsnorm_split<<<ROWS, 256>>>(x, n1_w, xnh, xnl);
    // qkv = x̂1 @ w_qkv^T
    gemm_mma<<<dim3(3 * DMODEL / 128, ROWS / 128), 256, GEMM_SMEM>>>(
        xnh, xnl, DMODEL, wqh, wql, DMODEL, nullptr, qkv, 3 * DMODEL, DMODEL);
    // attention (fp32)
    flash_attn<<<dim3(LEN / 64, BSZ * NHEAD), 128, FLASH_SMEM>>>(qkv, attn);
    // attn -> bf16 hi/lo
    convert_split<<<ROWS, 256>>>(attn, DMODEL, ROWS, DMODEL, ath, atl, DMODEL);
    // x1 = x + attn @ w_o^T
    gemm_mma<<<dim3(DMODEL / 128, ROWS / 128), 256, GEMM_SMEM>>>(
        ath, atl, DMODEL, woh, wol, DMODEL, x, x1, DMODEL, DMODEL);
    // x̂2 = rmsnorm(x1, n2)
    rmsnorm_split<<<ROWS, 256>>>(x1, n2_w, xnh, xnl);
    // h1 = x̂2 @ w1^T ; h3 = x̂2 @ w3^T   (N padded to 2816)
    gemm_mma<<<dim3(FF_PAD / 128, ROWS / 128), 256, GEMM_SMEM>>>(
        xnh, xnl, DMODEL, w1h, w1l, DMODEL, nullptr, h1, FF_PAD, DMODEL);
    gemm_mma<<<dim3(FF_PAD / 128, ROWS / 128), 256, GEMM_SMEM>>>(
        xnh, xnl, DMODEL, w3h, w3l, DMODEL, nullptr, h3, FF_PAD, DMODEL);
    // gated = silu(h1)*h3 -> bf16 hi/lo
    silu_gate_split<<<ROWS, 256>>>(h1, h3, gth, gtl);
    // out = x1 + gated @ w2^T   (K padded to 2816)
    gemm_mma<<<dim3(DMODEL / 128, ROWS / 128), 256, GEMM_SMEM>>>(
        gth, gtl, FF_PAD, w2h, w2l, FF_PAD, x1, out, DMODEL, FF_PAD);
}

// round 5
// speedup vs baseline: 2.7344x; 1.5070x over previous
#include <cuda_runtime.h>
#include <cuda_bf16.h>
#include <math.h>
#include <stdint.h>

// ---------------------------------------------------------------------------
// Problem constants
// ---------------------------------------------------------------------------
#define BSZ    2
#define LEN    2048
#define DMODEL 1024
#define NHEAD  16
#define DK     64
#define FF     2730
#define FF_PAD 2816                // 22*128
#define ROWS   (BSZ * LEN)         // 4096
#define EPS    1e-6f

// ---------------------------------------------------------------------------
// Scratch (device globals: allocation-free)
// ---------------------------------------------------------------------------
__device__ float g_qkv [(size_t)ROWS * 3 * DMODEL];
__device__ float g_x1  [(size_t)ROWS * DMODEL];
__device__ float g_h1  [(size_t)ROWS * FF_PAD];
__device__ float g_h3  [(size_t)ROWS * FF_PAD];

__device__ __nv_bfloat16 g_qb [(size_t)BSZ * NHEAD * LEN * DK];   // scaled Q, per-head
__device__ __nv_bfloat16 g_kb [(size_t)BSZ * NHEAD * LEN * DK];   // K per-head
__device__ __nv_bfloat16 g_vtb[(size_t)BSZ * NHEAD * DK * LEN];   // V transposed per-head

__device__ __nv_bfloat16 g_xn_h[(size_t)ROWS * DMODEL];
__device__ __nv_bfloat16 g_xn_l[(size_t)ROWS * DMODEL];
__device__ __nv_bfloat16 g_at_h[(size_t)ROWS * DMODEL];
__device__ __nv_bfloat16 g_at_l[(size_t)ROWS * DMODEL];
__device__ __nv_bfloat16 g_gt_h[(size_t)ROWS * FF_PAD];
__device__ __nv_bfloat16 g_gt_l[(size_t)ROWS * FF_PAD];

__device__ __nv_bfloat16 g_wq_h[(size_t)3 * DMODEL * DMODEL];
__device__ __nv_bfloat16 g_wq_l[(size_t)3 * DMODEL * DMODEL];
__device__ __nv_bfloat16 g_wo_h[(size_t)DMODEL * DMODEL];
__device__ __nv_bfloat16 g_wo_l[(size_t)DMODEL * DMODEL];
__device__ __nv_bfloat16 g_w1_h[(size_t)FF_PAD * DMODEL];
__device__ __nv_bfloat16 g_w1_l[(size_t)FF_PAD * DMODEL];
__device__ __nv_bfloat16 g_w3_h[(size_t)FF_PAD * DMODEL];
__device__ __nv_bfloat16 g_w3_l[(size_t)FF_PAD * DMODEL];
__device__ __nv_bfloat16 g_w2_h[(size_t)DMODEL * FF_PAD];
__device__ __nv_bfloat16 g_w2_l[(size_t)DMODEL * FF_PAD];

// ---------------------------------------------------------------------------
// PTX helpers (sm_80+ portable)
// ---------------------------------------------------------------------------
__device__ __forceinline__ uint32_t smem_u32(const void* p) {
    uint32_t a;
    asm("{ .reg .u64 t; cvta.to.shared.u64 t, %1; cvt.u32.u64 %0, t; }"
        : "=r"(a) : "l"(p));
    return a;
}
__device__ __forceinline__ void cp16(uint32_t dst, const void* src) {
    asm volatile("cp.async.cg.shared.global [%0], [%1], 16;" :: "r"(dst), "l"(src));
}
__device__ __forceinline__ void ldmx4(uint32_t r[4], uint32_t addr) {
    asm volatile("ldmatrix.sync.aligned.m8n8.x4.shared.b16 {%0,%1,%2,%3}, [%4];"
                 : "=r"(r[0]), "=r"(r[1]), "=r"(r[2]), "=r"(r[3]) : "r"(addr));
}
__device__ __forceinline__ void mma_bf16(float c[4], const uint32_t a[4],
                                         uint32_t b0, uint32_t b1) {
    asm volatile(
        "mma.sync.aligned.m16n8k16.row.col.f32.bf16.bf16.f32 "
        "{%0,%1,%2,%3}, {%4,%5,%6,%7}, {%8,%9}, {%0,%1,%2,%3};"
        : "+f"(c[0]), "+f"(c[1]), "+f"(c[2]), "+f"(c[3])
        : "r"(a[0]), "r"(a[1]), "r"(a[2]), "r"(a[3]), "r"(b0), "r"(b1));
}
__device__ __forceinline__ uint32_t pk_bf16(float lo, float hi) {
    uint32_t r;
    asm("cvt.rn.bf16x2.f32 %0, %1, %2;" : "=r"(r) : "f"(hi), "f"(lo));
    return r;
}
__device__ __forceinline__ uint32_t swz(uint32_t off) {   // 128B-row swizzle
    return off ^ ((off >> 3) & 0x70);
}

// ---------------------------------------------------------------------------
// bf16 hi/lo 3-pass MMA GEMM (unchanged from round 4)
// ---------------------------------------------------------------------------
#define LDS_H   40
#define TILE_SB (128 * LDS_H * 2)
#define STG_SB  (4 * TILE_SB)
#define GEMM_SMEM (2 * STG_SB)

__global__ void __launch_bounds__(256, 1)
gemm_mma(const __nv_bfloat16* __restrict__ Ah, const __nv_bfloat16* __restrict__ Al,
         int lda,
         const __nv_bfloat16* __restrict__ Bh, const __nv_bfloat16* __restrict__ Bl,
         int ldb,
         const float* __restrict__ R, float* __restrict__ C, int ldc, int K)
{
    extern __shared__ char smraw[];
    uint32_t s0 = smem_u32(smraw);

    int tid = threadIdx.x;
    int wid = tid >> 5;
    int lane = tid & 31;
    int wm = wid >> 2;
    int wn = wid & 3;

    size_t m0 = (size_t)blockIdx.y * 128;
    size_t n0 = (size_t)blockIdx.x * 128;

    float acc[4][4][4];
    #pragma unroll
    for (int i = 0; i < 4; i++)
        #pragma unroll
        for (int j = 0; j < 4; j++)
            #pragma unroll
            for (int q = 0; q < 4; q++) acc[i][j][q] = 0.f;

    const int T = K >> 5;

    auto load_stage = [&](int buf, int k0) {
        uint32_t sbase = s0 + buf * STG_SB;
        #pragma unroll
        for (int i = 0; i < 2; i++) {
            int c = tid + i * 256;
            int row = c >> 2;
            int c16 = c & 3;
            uint32_t off = (uint32_t)(row * (LDS_H * 2) + c16 * 16);
            size_t ga = (size_t)(m0 + row) * lda + k0 + c16 * 8;
            size_t gb = (size_t)(n0 + row) * ldb + k0 + c16 * 8;
            cp16(sbase + off,               Ah + ga);
            cp16(sbase + TILE_SB + off,     Al + ga);
            cp16(sbase + 2 * TILE_SB + off, Bh + gb);
            cp16(sbase + 3 * TILE_SB + off, Bl + gb);
        }
        asm volatile("cp.async.commit_group;");
    };

    load_stage(0, 0);

    int lr = lane & 15;
    int lc = (lane >> 4) * 8;

    for (int t = 0; t < T; t++) {
        if (t + 1 < T) {
            load_stage((t + 1) & 1, (t + 1) << 5);
            asm volatile("cp.async.wait_group 1;");
        } else {
            asm volatile("cp.async.wait_group 0;");
        }
        __syncthreads();

        uint32_t base = s0 + (t & 1) * STG_SB;
        #pragma unroll
        for (int kk = 0; kk < 2; kk++) {
            int k16 = kk * 16;
            uint32_t ah[4][4], al[4][4], bh[2][4], bl[2][4];
            #pragma unroll
            for (int mi = 0; mi < 4; mi++) {
                uint32_t aoff = (uint32_t)((wm * 64 + mi * 16 + lr) * (LDS_H * 2) +
                                           (k16 + lc) * 2);
                ldmx4(ah[mi], base + aoff);
                ldmx4(al[mi], base + TILE_SB + aoff);
            }
            #pragma unroll
            for (int ni = 0; ni < 2; ni++) {
                uint32_t boff = (uint32_t)((wn * 32 + ni * 16 + lr) * (LDS_H * 2) +
                                           (k16 + lc) * 2);
                ldmx4(bh[ni], base + 2 * TILE_SB + boff);
                ldmx4(bl[ni], base + 3 * TILE_SB + boff);
            }
            #pragma unroll
            for (int mi = 0; mi < 4; mi++) {
                #pragma unroll
                for (int nj = 0; nj < 4; nj++) {
                    int ni = nj >> 1;
                    int sel = nj & 1;
                    mma_bf16(acc[mi][nj], ah[mi], bh[ni][sel], bh[ni][sel + 2]);
                    mma_bf16(acc[mi][nj], ah[mi], bl[ni][sel], bl[ni][sel + 2]);
                    mma_bf16(acc[mi][nj], al[mi], bh[ni][sel], bh[ni][sel + 2]);
                }
            }
        }
        __syncthreads();
    }

    int qr = lane >> 2;
    int qc = (lane & 3) * 2;
    #pragma unroll
    for (int mi = 0; mi < 4; mi++) {
        #pragma unroll
        for (int nj = 0; nj < 4; nj++) {
            size_t m = m0 + wm * 64 + mi * 16 + qr;
            size_t n = n0 + wn * 32 + nj * 8 + qc;
            float2 v0 = make_float2(acc[mi][nj][0], acc[mi][nj][1]);
            float2 v1 = make_float2(acc[mi][nj][2], acc[mi][nj][3]);
            if (R) {
                float2 r0 = *(const float2*)(R + m * ldc + n);
                float2 r1 = *(const float2*)(R + (m + 8) * ldc + n);
                v0.x += r0.x; v0.y += r0.y;
                v1.x += r1.x; v1.y += r1.y;
            }
            *(float2*)(C + m * ldc + n) = v0;
            *(float2*)(C + (m + 8) * ldc + n) = v1;
        }
    }
}

// ---------------------------------------------------------------------------
// Split qkv -> per-head bf16 Q (scaled 0.125) and K
// ---------------------------------------------------------------------------
__global__ void __launch_bounds__(256) split_qk(const float* __restrict__ qkv,
                                                __nv_bfloat16* __restrict__ qb,
                                                __nv_bfloat16* __restrict__ kb)
{
    int row = blockIdx.x;               // b*LEN + l
    int b = row >> 11;
    int l = row & 2047;
    int t = threadIdx.x;
    int c = t * 4;                      // 0..1020
    int h = c >> 6;
    int d = c & 63;

    size_t dst = ((size_t)(b * NHEAD + h) * LEN + l) * DK + d;
    const float* src = qkv + (size_t)row * (3 * DMODEL);

    float4 q4 = *(const float4*)(src + c);
    float4 k4 = *(const float4*)(src + DMODEL + c);
    uint32_t* qo = (uint32_t*)(g_qb + 0, qb + dst);
    uint32_t* ko = (uint32_t*)(kb + dst);
    qo[0] = pk_bf16(q4.x * 0.125f, q4.y * 0.125f);
    qo[1] = pk_bf16(q4.z * 0.125f, q4.w * 0.125f);
    ko[0] = pk_bf16(k4.x, k4.y);
    ko[1] = pk_bf16(k4.z, k4.w);
}

// ---------------------------------------------------------------------------
// Transpose V per head: vtb[b,h,d,l] bf16
// ---------------------------------------------------------------------------
__global__ void __launch_bounds__(256) transpose_v(const float* __restrict__ qkv,
                                                   __nv_bfloat16* __restrict__ vtb)
{
    __shared__ float st[64][65];
    int bh = blockIdx.y;
    int b = bh >> 4;
    int h = bh & 15;
    int l0 = blockIdx.x * 64;
    int t = threadIdx.x;

    // load 64 rows (l) x 64 cols (d)
    {
        int r = t >> 2;
        int c0 = (t & 3) * 16;
        const float* src = qkv + ((size_t)(b * LEN + l0 + r)) * (3 * DMODEL) +
                           2 * DMODEL + h * DK + c0;
        #pragma unroll
        for (int i = 0; i < 4; i++) {
            float4 v = *(const float4*)(src + i * 4);
            st[c0 + i * 4 + 0][r] = v.x;
            st[c0 + i * 4 + 1][r] = v.y;
            st[c0 + i * 4 + 2][r] = v.z;
            st[c0 + i * 4 + 3][r] = v.w;
        }
    }
    __syncthreads();
    // write rows of vt: d fixed, l contiguous
    {
        int d = t >> 2;
        int l4 = (t & 3) * 16;
        uint32_t* dst = (uint32_t*)(vtb + ((size_t)bh * DK + d) * LEN + l0 + l4);
        #pragma unroll
        for (int i = 0; i < 8; i++)
            dst[i] = pk_bf16(st[d][l4 + i * 2], st[d][l4 + i * 2 + 1]);
    }
}

// ---------------------------------------------------------------------------
// Flash attention v2: bf16 HMMA, online softmax, hi/lo bf16 output.
// grid (LEN/64, B*NHEAD), 128 threads (4 warps x 16 Q rows).
// ---------------------------------------------------------------------------
__global__ void __launch_bounds__(128)
flash_mma(const __nv_bfloat16* __restrict__ qb,
          const __nv_bfloat16* __restrict__ kb,
          const __nv_bfloat16* __restrict__ vtb,
          __nv_bfloat16* __restrict__ ath,
          __nv_bfloat16* __restrict__ atl)
{
    __shared__ __nv_bfloat16 Qs[64 * 64];
    __shared__ __nv_bfloat16 Ks[2][64 * 64];
    __shared__ __nv_bfloat16 Vs[2][64 * 64];

    int bh = blockIdx.y;
    int b = bh >> 4;
    int h = bh & 15;
    int q0 = blockIdx.x * 64;
    int tid = threadIdx.x;
    int lane = tid & 31;
    int w = tid >> 5;

    const __nv_bfloat16* qB = qb + (size_t)bh * LEN * DK;
    const __nv_bfloat16* kB = kb + (size_t)bh * LEN * DK;
    const __nv_bfloat16* vB = vtb + (size_t)bh * DK * LEN;

    uint32_t qs = smem_u32(Qs);
    uint32_t ks0 = smem_u32(Ks);
    uint32_t vs0 = smem_u32(Vs);

    // Q tile (512 x 16B chunks)
    #pragma unroll
    for (int i = 0; i < 4; i++) {
        int c = tid + i * 128;
        int r = c >> 3, ch = c & 7;
        uint32_t off = (uint32_t)(r * 128 + ch * 16);
        cp16(qs + swz(off), qB + (size_t)(q0 + r) * DK + ch * 8);
    }

    auto loadKV = [&](int buf, int kt) {
        uint32_t kd = ks0 + buf * 8192;
        uint32_t vd = vs0 + buf * 8192;
        #pragma unroll
        for (int i = 0; i < 4; i++) {
            int c = tid + i * 128;
            int r = c >> 3, ch = c & 7;
            uint32_t sw = swz((uint32_t)(r * 128 + ch * 16));
            cp16(kd + sw, kB + (size_t)(kt * 64 + r) * DK + ch * 8);
            cp16(vd + sw, vB + (size_t)r * LEN + kt * 64 + ch * 8);
        }
        asm volatile("cp.async.commit_group;");
    };
    loadKV(0, 0);   // group 0 includes Q + stage0

    float m_i[2] = {-1e30f, -1e30f};
    float l_i[2] = {0.f, 0.f};
    float o[8][4];
    #pragma unroll
    for (int j = 0; j < 8; j++)
        #pragma unroll
        for (int q = 0; q < 4; q++) o[j][q] = 0.f;

    uint32_t qf[4][4];
    int lr = lane & 15;
    int lc = (lane >> 4) * 8;

    for (int kt = 0; kt < LEN / 64; kt++) {
        if (kt + 1 < LEN / 64) {
            loadKV((kt + 1) & 1, kt + 1);
            asm volatile("cp.async.wait_group 1;");
        } else {
            asm volatile("cp.async.wait_group 0;");
        }
        __syncthreads();

        if (kt == 0) {
            #pragma unroll
            for (int t4 = 0; t4 < 4; t4++) {
                uint32_t off = (uint32_t)((w * 16 + lr) * 128 + (t4 * 16 + lc) * 2);
                ldmx4(qf[t4], qs + swz(off));
            }
        }

        uint32_t kbse = ks0 + (kt & 1) * 8192;
        uint32_t vbse = vs0 + (kt & 1) * 8192;

        // S = Q K^T
        float s[8][4];
        #pragma unroll
        for (int j = 0; j < 8; j++)
            #pragma unroll
            for (int q = 0; q < 4; q++) s[j][q] = 0.f;
        #pragma unroll
        for (int t4 = 0; t4 < 4; t4++) {
            #pragma unroll
            for (int ng = 0; ng < 4; ng++) {
                uint32_t off = (uint32_t)((ng * 16 + lr) * 128 + (t4 * 16 + lc) * 2);
                uint32_t kf[4];
                ldmx4(kf, kbse + swz(off));
                mma_bf16(s[ng * 2],     qf[t4], kf[0], kf[2]);
                mma_bf16(s[ng * 2 + 1], qf[t4], kf[1], kf[3]);
            }
        }

        // online softmax (rows qr and qr+8)
        #pragma unroll
        for (int hr = 0; hr < 2; hr++) {
            float mx = -1e30f;
            #pragma unroll
            for (int j = 0; j < 8; j++)
                mx = fmaxf(mx, fmaxf(s[j][hr * 2], s[j][hr * 2 + 1]));
            mx = fmaxf(mx, __shfl_xor_sync(0xffffffffu, mx, 1));
            mx = fmaxf(mx, __shfl_xor_sync(0xffffffffu, mx, 2));
            float mn = fmaxf(m_i[hr], mx);
            float corr = __expf(m_i[hr] - mn);
            m_i[hr] = mn;
            float rs = 0.f;
            #pragma unroll
            for (int j = 0; j < 8; j++) {
                s[j][hr * 2]     = __expf(s[j][hr * 2] - mn);
                s[j][hr * 2 + 1] = __expf(s[j][hr * 2 + 1] - mn);
                rs += s[j][hr * 2] + s[j][hr * 2 + 1];
            }
            rs += __shfl_xor_sync(0xffffffffu, rs, 1);
            rs += __shfl_xor_sync(0xffffffffu, rs, 2);
            l_i[hr] = l_i[hr] * corr + rs;
            #pragma unroll
            for (int j = 0; j < 8; j++) {
                o[j][hr * 2] *= corr;
                o[j][hr * 2 + 1] *= corr;
            }
        }

        // P -> bf16 A-frags
        uint32_t pa[4][4];
        #pragma unroll
        for (int t4 = 0; t4 < 4; t4++) {
            pa[t4][0] = pk_bf16(s[2 * t4][0],     s[2 * t4][1]);
            pa[t4][1] = pk_bf16(s[2 * t4][2],     s[2 * t4][3]);
            pa[t4][2] = pk_bf16(s[2 * t4 + 1][0], s[2 * t4 + 1][1]);
            pa[t4][3] = pk_bf16(s[2 * t4 + 1][2], s[2 * t4 + 1][3]);
        }

        // O += P V  (V from transposed smem tile)
        #pragma unroll
        for (int t4 = 0; t4 < 4; t4++) {
            #pragma unroll
            for (int np = 0; np < 4; np++) {
                uint32_t off = (uint32_t)((np * 16 + ((lane >> 4) & 1) * 8 + (lane & 7)) * 128 +
                                          (t4 * 16 + ((lane >> 3) & 1) * 8) * 2);
                uint32_t vf[4];
                ldmx4(vf, vbse + swz(off));
                mma_bf16(o[np * 2],     pa[t4], vf[0], vf[1]);
                mma_bf16(o[np * 2 + 1], pa[t4], vf[2], vf[3]);
            }
        }
        __syncthreads();
    }

    // finalize: divide by l, write hi/lo bf16
    int qr = lane >> 2;
    int qc2 = (lane & 3) * 2;
    #pragma unroll
    for (int hr = 0; hr < 2; hr++) {
        float invl = 1.0f / l_i[hr];
        size_t gl = (size_t)b * LEN + q0 + w * 16 + qr + hr * 8;
        #pragma unroll
        for (int nt = 0; nt < 8; nt++) {
            float v0 = o[nt][hr * 2] * invl;
            float v1 = o[nt][hr * 2 + 1] * invl;
            __nv_bfloat16 h0 = __float2bfloat16(v0);
            __nv_bfloat16 h1 = __float2bfloat16(v1);
            float l0 = v0 - __bfloat162float(h0);
            float l1 = v1 - __bfloat162float(h1);
            size_t idx = gl * DMODEL + h * DK + nt * 8 + qc2;
            uint32_t hp = ((uint32_t)__bfloat16_as_ushort(h1) << 16) |
                          (uint32_t)__bfloat16_as_ushort(h0);
            *(uint32_t*)(ath + idx) = hp;
            *(uint32_t*)(atl + idx) = pk_bf16(l0, l1);
        }
    }
}

// ---------------------------------------------------------------------------
// fp32 -> bf16 hi/lo split with zero padding (generic)
// ---------------------------------------------------------------------------
__global__ void __launch_bounds__(256) convert_split(const float* __restrict__ src,
                                                     int ld_src, int rows_src,
                                                     int cols_src,
                                                     __nv_bfloat16* __restrict__ hi,
                                                     __nv_bfloat16* __restrict__ lo,
                                                     int ld_dst)
{
    int r = blockIdx.x;
    const float* s = src + (size_t)r * ld_src;
    __nv_bfloat16* ph = hi + (size_t)r * ld_dst;
    __nv_bfloat16* pl = lo + (size_t)r * ld_dst;
    bool rv = r < rows_src;
    for (int c = threadIdx.x; c < ld_dst; c += 256) {
        float v = (rv && c < cols_src) ? s[c] : 0.f;
        __nv_bfloat16 h = __float2bfloat16(v);
        ph[c] = h;
        pl[c] = __float2bfloat16(v - __bfloat162float(h));
    }
}

// ---------------------------------------------------------------------------
// RMSNorm with fused hi/lo split output
// ---------------------------------------------------------------------------
__global__ void __launch_bounds__(256) rmsnorm_split(const float* __restrict__ x,
                                                     const float* __restrict__ w,
                                                     __nv_bfloat16* __restrict__ hi,
                                                     __nv_bfloat16* __restrict__ lo)
{
    int row = blockIdx.x;
    const float* xr = x + (size_t)row * DMODEL;
    int t = threadIdx.x;

    float4 v = ((const float4*)xr)[t];
    float ss = v.x * v.x + v.y * v.y + v.z * v.z + v.w * v.w;
    #pragma unroll
    for (int o = 16; o; o >>= 1) ss += __shfl_xor_sync(0xffffffffu, ss, o);
    __shared__ float sred[8];
    if ((t & 31) == 0) sred[t >> 5] = ss;
    __syncthreads();
    float tot = 0.f;
    #pragma unroll
    for (int i = 0; i < 8; i++) tot += sred[i];
    float inv = rsqrtf(tot * (1.0f / DMODEL) + EPS);

    float4 wv = ((const float4*)w)[t];
    float o4[4] = { v.x * inv * wv.x, v.y * inv * wv.y,
                    v.z * inv * wv.z, v.w * inv * wv.w };
    size_t base = (size_t)row * DMODEL + t * 4;
    #pragma unroll
    for (int j = 0; j < 4; j++) {
        __nv_bfloat16 h = __float2bfloat16(o4[j]);
        hi[base + j] = h;
        lo[base + j] = __float2bfloat16(o4[j] - __bfloat162float(h));
    }
}

// ---------------------------------------------------------------------------
// SwiGLU gate with fused hi/lo split
// ---------------------------------------------------------------------------
__global__ void __launch_bounds__(256) silu_gate_split(const float* __restrict__ h1,
                                                       const float* __restrict__ h3,
                                                       __nv_bfloat16* __restrict__ hi,
                                                       __nv_bfloat16* __restrict__ lo)
{
    int row = blockIdx.x;
    const float* a = h1 + (size_t)row * FF_PAD;
    const float* b = h3 + (size_t)row * FF_PAD;
    __nv_bfloat16* ph = hi + (size_t)row * FF_PAD;
    __nv_bfloat16* pl = lo + (size_t)row * FF_PAD;
    for (int c = threadIdx.x; c < FF_PAD; c += 256) {
        float v = a[c];
        float g = v / (1.0f + __expf(-v)) * b[c];
        __nv_bfloat16 h = __float2bfloat16(g);
        ph[c] = h;
        pl[c] = __float2bfloat16(g - __bfloat162float(h));
    }
}

// ---------------------------------------------------------------------------
// Launch
// ---------------------------------------------------------------------------
extern "C" void kernel_launch(void* const* d_in, const int* in_sizes, int n_in,
                              void* d_out, int out_size)
{
    const float* x     = (const float*)d_in[0];
    const float* w_qkv = (const float*)d_in[1];
    const float* w_o   = (const float*)d_in[2];
    const float* n1_w  = (const float*)d_in[3];
    const float* n2_w  = (const float*)d_in[4];
    const float* w1    = (const float*)d_in[5];
    const float* w2    = (const float*)d_in[6];
    const float* w3    = (const float*)d_in[7];
    float* out = (float*)d_out;

    cudaFuncSetAttribute(gemm_mma, cudaFuncAttributeMaxDynamicSharedMemorySize,
                         GEMM_SMEM);

    float *qkv, *x1, *h1, *h3;
    cudaGetSymbolAddress((void**)&qkv, g_qkv);
    cudaGetSymbolAddress((void**)&x1,  g_x1);
    cudaGetSymbolAddress((void**)&h1,  g_h1);
    cudaGetSymbolAddress((void**)&h3,  g_h3);

    __nv_bfloat16 *qb, *kb, *vtb;
    cudaGetSymbolAddress((void**)&qb,  g_qb);
    cudaGetSymbolAddress((void**)&kb,  g_kb);
    cudaGetSymbolAddress((void**)&vtb, g_vtb);

    __nv_bfloat16 *xnh, *xnl, *ath, *atl, *gth, *gtl;
    __nv_bfloat16 *wqh, *wql, *woh, *wol, *w1h, *w1l, *w3h, *w3l, *w2h, *w2l;
    cudaGetSymbolAddress((void**)&xnh, g_xn_h); cudaGetSymbolAddress((void**)&xnl, g_xn_l);
    cudaGetSymbolAddress((void**)&ath, g_at_h); cudaGetSymbolAddress((void**)&atl, g_at_l);
    cudaGetSymbolAddress((void**)&gth, g_gt_h); cudaGetSymbolAddress((void**)&gtl, g_gt_l);
    cudaGetSymbolAddress((void**)&wqh, g_wq_h); cudaGetSymbolAddress((void**)&wql, g_wq_l);
    cudaGetSymbolAddress((void**)&woh, g_wo_h); cudaGetSymbolAddress((void**)&wol, g_wo_l);
    cudaGetSymbolAddress((void**)&w1h, g_w1_h); cudaGetSymbolAddress((void**)&w1l, g_w1_l);
    cudaGetSymbolAddress((void**)&w3h, g_w3_h); cudaGetSymbolAddress((void**)&w3l, g_w3_l);
    cudaGetSymbolAddress((void**)&w2h, g_w2_h); cudaGetSymbolAddress((void**)&w2l, g_w2_l);

    // weight conversions
    convert_split<<<3 * DMODEL, 256>>>(w_qkv, DMODEL, 3 * DMODEL, DMODEL, wqh, wql, DMODEL);
    convert_split<<<DMODEL, 256>>>(w_o, DMODEL, DMODEL, DMODEL, woh, wol, DMODEL);
    convert_split<<<FF_PAD, 256>>>(w1, DMODEL, FF, DMODEL, w1h, w1l, DMODEL);
    convert_split<<<FF_PAD, 256>>>(w3, DMODEL, FF, DMODEL, w3h, w3l, DMODEL);
    convert_split<<<DMODEL, 256>>>(w2, FF, DMODEL, FF, w2h, w2l, FF_PAD);

    // x̂1 = rmsnorm(x, n1)
    rmsnorm_split<<<ROWS, 256>>>(x, n1_w, xnh, xnl);
    // qkv = x̂1 @ w_qkv^T
    gemm_mma<<<dim3(3 * DMODEL / 128, ROWS / 128), 256, GEMM_SMEM>>>(
        xnh, xnl, DMODEL, wqh, wql, DMODEL, nullptr, qkv, 3 * DMODEL, DMODEL);
    // qkv -> per-head bf16 buffers
    split_qk<<<ROWS, 256>>>(qkv, qb, kb);
    transpose_v<<<dim3(LEN / 64, BSZ * NHEAD), 256>>>(qkv, vtb);
    // attention (bf16 HMMA) -> ath/atl directly
    flash_mma<<<dim3(LEN / 64, BSZ * NHEAD), 128>>>(qb, kb, vtb, ath, atl);
    // x1 = x + attn @ w_o^T
    gemm_mma<<<dim3(DMODEL / 128, ROWS / 128), 256, GEMM_SMEM>>>(
        ath, atl, DMODEL, woh, wol, DMODEL, x, x1, DMODEL, DMODEL);
    // x̂2 = rmsnorm(x1, n2)
    rmsnorm_split<<<ROWS, 256>>>(x1, n2_w, xnh, xnl);
    // h1 = x̂2 @ w1^T ; h3 = x̂2 @ w3^T
    gemm_mma<<<dim3(FF_PAD / 128, ROWS / 128), 256, GEMM_SMEM>>>(
        xnh, xnl, DMODEL, w1h, w1l, DMODEL, nullptr, h1, FF_PAD, DMODEL);
    gemm_mma<<<dim3(FF_PAD / 128, ROWS / 128), 256, GEMM_SMEM>>>(
        xnh, xnl, DMODEL, w3h, w3l, DMODEL, nullptr, h3, FF_PAD, DMODEL);
    // gated = silu(h1)*h3 -> bf16 hi/lo
    silu_gate_split<<<ROWS, 256>>>(h1, h3, gth, gtl);
    // out = x1 + gated @ w2^T
    gemm_mma<<<dim3(DMODEL / 128, ROWS / 128), 256, GEMM_SMEM>>>(
        gth, gtl, FF_PAD, w2h, w2l, FF_PAD, x1, out, DMODEL, FF_PAD);
}